// round 11
// baseline (speedup 1.0000x reference)
#include <cuda_runtime.h>
#include <math.h>

#define Bc 4
#define Nc 5
#define Cc 64
#define Hc 100
#define Wc 252
#define FULLMASK 0xFFFFFFFFu

static constexpr int HW  = Hc * Wc;      // 25200
static constexpr int CHW = Cc * HW;      // 1612800
static constexpr int OUT_MAIN = Bc * CHW;
static constexpr int C_CHUNKS = 8;
static constexpr int C_PER    = Cc / C_CHUNKS;   // 8

__global__ __launch_bounds__(256, 4) void where2comm_fuse_kernel(
    const float* __restrict__ x,          // [B*N, C, H, W]
    const float* __restrict__ tmat,       // [B, N, N, 2, 3]
    float* __restrict__ out,              // [B, C, H, W] (+ scalar tail)
    int out_size)
{
    const int h  = blockIdx.x;
    const int b  = blockIdx.y;
    const int c0 = blockIdx.z * C_PER;
    const int wt = threadIdx.x;

    // Zero any tail (communication_rates scalar) once.
    if (b == 0 && h == 0 && blockIdx.z == 0) {
        for (int i = OUT_MAIN + threadIdx.x; i < out_size; i += blockDim.x)
            out[i] = 0.0f;
    }

    // No early return: shuffles below need all 32 lanes. Inactive lanes
    // (wt 252..255) compute on clamped w and skip the store.
    const bool active = (wt < Wc);
    const int  w = active ? wt : (Wc - 1);

    const float gx = (2.0f * (float)w + 1.0f) / (float)Wc - 1.0f;
    const float gy = (2.0f * (float)h + 1.0f) / (float)Hc - 1.0f;

    float m[C_PER];
#pragma unroll
    for (int c = 0; c < C_PER; c++) m[c] = -INFINITY;

#pragma unroll
    for (int n = 0; n < Nc; n++) {
        // theta = pairwise_t_matrix[b, 0, n, :, :]  -> 6 floats
        const float* th = tmat + ((size_t)b * Nc * Nc + n) * 6;
        const float t0 = __ldg(th + 0);
        const float t1 = __ldg(th + 1);
        const float t2 = __ldg(th + 2);
        const float t3 = __ldg(th + 3);
        const float t4 = __ldg(th + 4);
        const float t5 = __ldg(th + 5);

        const float cx = t0 * gx + t1 * gy + t2;
        const float cy = t3 * gx + t4 * gy + t5;
        const float ix = ((cx + 1.0f) * (float)Wc - 1.0f) * 0.5f;
        const float iy = ((cy + 1.0f) * (float)Hc - 1.0f) * 0.5f;

        const float x0f = floorf(ix);
        const float y0f = floorf(iy);
        const float wx1 = ix - x0f;
        const float wy1 = iy - y0f;
        const float wx0 = 1.0f - wx1;
        const float wy0 = 1.0f - wy1;

        const int x0 = (int)x0f;
        const int y0 = (int)y0f;
        const int x1 = x0 + 1;
        const int y1 = y0 + 1;

        const bool vx0 = (x0 >= 0) & (x0 <= Wc - 1);
        const bool vx1 = (x1 >= 0) & (x1 <= Wc - 1);
        const bool vy0 = (y0 >= 0) & (y0 <= Hc - 1);
        const bool vy1 = (y1 >= 0) & (y1 <= Hc - 1);

        const int x0c = min(max(x0, 0), Wc - 1);
        const int x1c = min(max(x1, 0), Wc - 1);
        const int y0c = min(max(y0, 0), Hc - 1);
        const int y1c = min(max(y1, 0), Hc - 1);

        const float w0 = (vx0 && vy0) ? wx0 * wy0 : 0.0f;
        const float w1 = (vx1 && vy0) ? wx1 * wy0 : 0.0f;
        const float w2 = (vx0 && vy1) ? wx0 * wy1 : 0.0f;
        const float w3 = (vx1 && vy1) ? wx1 * wy1 : 0.0f;

        // ---- paired x-taps: one float2 load covers taps (x0c, x1c) ----
        // Anchor at the valid x-tap; sel=1 iff both taps valid (x1c = xa+1).
        const int xa  = vx0 ? x0c : x1c;
        const int sel = (vx0 && vx1) ? 1 : 0;
        const int a0  = y0c * Wc + xa;      // row y0 anchor index
        const int a2  = y1c * Wc + xa;      // row y1 anchor index (same parity)
        const int fl  = a0 & 1;
        const int e0  = a0 & ~1;
        const int e2  = a2 & ~1;

        // Odd-parity lanes recover tap1 from neighbor lane's u.x; validate.
        const int e0n = __shfl_down_sync(FULLMASK, e0, 1);
        const int e2n = __shfl_down_sync(FULLMASK, e2, 1);
        const bool need0 = sel && fl && (e0n != a0 + 1);  // incl. lane 31
        const bool need2 = sel && fl && (e2n != a2 + 1);
        const bool anyfix = __any_sync(FULLMASK, need0 || need2);

        const float*  bp = x + (size_t)((b * Nc + n) * CHW + c0 * HW);
        const float2* p0 = (const float2*)(bp + e0);
        const float2* p2 = (const float2*)(bp + e2);

#pragma unroll
        for (int c = 0; c < C_PER; c++) {
            const int coff2 = c * (HW / 2);
            const float2 u0 = __ldg(p0 + coff2);
            const float2 u2 = __ldg(p2 + coff2);

            const float n0 = __shfl_down_sync(FULLMASK, u0.x, 1);
            const float n2 = __shfl_down_sync(FULLMASK, u2.x, 1);

            const float t00 = fl ? u0.y : u0.x;            // tap (x0,y0)
            const float t10 = fl ? u2.y : u2.x;            // tap (x0,y1)
            float t01 = sel ? (fl ? n0 : u0.y) : t00;      // tap (x1,y0)
            float t11 = sel ? (fl ? n2 : u2.y) : t10;      // tap (x1,y1)

            if (anyfix) {                                   // warp-uniform skip
                if (need0) t01 = __ldg(bp + a0 + 1 + c * HW);
                if (need2) t11 = __ldg(bp + a2 + 1 + c * HW);
            }

            float v = w0 * t00;
            v = fmaf(w1, t01, v);
            v = fmaf(w2, t10, v);
            v = fmaf(w3, t11, v);
            m[c] = fmaxf(m[c], v);
        }
    }

    if (active) {
        float* op = out + (size_t)b * CHW + (size_t)c0 * HW + h * Wc + w;
#pragma unroll
        for (int c = 0; c < C_PER; c++)
            op[(size_t)c * HW] = m[c];
    }
}

extern "C" void kernel_launch(void* const* d_in, const int* in_sizes, int n_in,
                              void* d_out, int out_size)
{
    // Inputs (metadata order): x, rm, record_len, pairwise_t_matrix
    const float* x    = (const float*)d_in[0];
    const float* tmat = (const float*)d_in[3];
    float* out = (float*)d_out;

    dim3 grid(Hc, Bc, C_CHUNKS);
    where2comm_fuse_kernel<<<grid, 256>>>(x, tmat, out, out_size);
}

// round 12
// speedup vs baseline: 1.8780x; 1.8780x over previous
#include <cuda_runtime.h>
#include <math.h>

#define Bc 4
#define Nc 5
#define Cc 64
#define Hc 100
#define Wc 252

static constexpr int HW  = Hc * Wc;      // 25200
static constexpr int CHW = Cc * HW;      // 1612800
static constexpr int OUT_MAIN = Bc * CHW;
static constexpr int XTOT = Bc * Nc * CHW;       // total elements of x
static constexpr int C_CHUNKS = 8;
static constexpr int C_PER    = Cc / C_CHUNKS;   // 8

__global__ __launch_bounds__(256, 4) void where2comm_fuse_kernel(
    const float* __restrict__ x,          // [B*N, C, H, W]
    const float* __restrict__ tmat,       // [B, N, N, 2, 3]
    float* __restrict__ out,              // [B, C, H, W] (+ scalar tail)
    int out_size)
{
    const int h  = blockIdx.x;
    const int b  = blockIdx.y;
    const int c0 = blockIdx.z * C_PER;
    const int w  = threadIdx.x;

    // Zero any tail (communication_rates scalar) once.
    if (b == 0 && h == 0 && blockIdx.z == 0) {
        for (int i = OUT_MAIN + threadIdx.x; i < out_size; i += blockDim.x)
            out[i] = 0.0f;
    }
    if (w >= Wc) return;

    const float gx = (2.0f * (float)w + 1.0f) / (float)Wc - 1.0f;
    const float gy = (2.0f * (float)h + 1.0f) / (float)Hc - 1.0f;

    float m[C_PER];
#pragma unroll
    for (int c = 0; c < C_PER; c++) m[c] = -INFINITY;

#pragma unroll
    for (int n = 0; n < Nc; n++) {
        // theta = pairwise_t_matrix[b, 0, n, :, :]  -> 6 floats
        const float* th = tmat + ((size_t)b * Nc * Nc + n) * 6;
        const float t0 = __ldg(th + 0);
        const float t1 = __ldg(th + 1);
        const float t2 = __ldg(th + 2);
        const float t3 = __ldg(th + 3);
        const float t4 = __ldg(th + 4);
        const float t5 = __ldg(th + 5);

        const float cx = t0 * gx + t1 * gy + t2;
        const float cy = t3 * gx + t4 * gy + t5;
        const float ix = ((cx + 1.0f) * (float)Wc - 1.0f) * 0.5f;
        const float iy = ((cy + 1.0f) * (float)Hc - 1.0f) * 0.5f;

        const float x0f = floorf(ix);
        const float y0f = floorf(iy);
        const float wx1 = ix - x0f;
        const float wy1 = iy - y0f;
        const float wx0 = 1.0f - wx1;
        const float wy0 = 1.0f - wy1;

        const int x0 = (int)x0f;
        const int y0 = (int)y0f;
        const int x1 = x0 + 1;
        const int y1 = y0 + 1;

        const bool vx0 = (x0 >= 0) & (x0 <= Wc - 1);
        const bool vx1 = (x1 >= 0) & (x1 <= Wc - 1);
        const bool vy0 = (y0 >= 0) & (y0 <= Hc - 1);
        const bool vy1 = (y1 >= 0) & (y1 <= Hc - 1);

        const int x0c = min(max(x0, 0), Wc - 1);
        const int x1c = min(max(x1, 0), Wc - 1);
        const int y0c = min(max(y0, 0), Hc - 1);
        const int y1c = min(max(y1, 0), Hc - 1);

        const float w0 = (vx0 && vy0) ? wx0 * wy0 : 0.0f;
        const float w1 = (vx1 && vy0) ? wx1 * wy0 : 0.0f;
        const float w2 = (vx0 && vy1) ? wx0 * wy1 : 0.0f;
        const float w3 = (vx1 && vy1) ? wx1 * wy1 : 0.0f;

        // ---- LDG.64 tap pairs: taps {x0c, x1c} live in floats [e, e+3] ----
        // a0/a2 have the same parity (Wc even), dx = x1c - x0c in {0,1}.
        const int dx  = x1c - x0c;
        const int a0  = y0c * Wc + x0c;
        const int a2  = y1c * Wc + x0c;
        const int odd = a0 & 1;
        const int e0  = a0 - odd;
        const int e2  = a2 - odd;

        const int gbase = (b * Nc + n) * CHW + c0 * HW;

        // v-load OOB clamp (only reachable at the absolute end of x, where
        // analysis shows v is never consumed; clamp keeps the read in-bounds).
        const int vmax = XTOT - gbase - (C_PER - 1) * HW - 4;
        const int f0   = (e0 <= vmax) ? e0 + 2 : e0;
        const int f2   = (e2 <= vmax) ? e2 + 2 : e2;

        const float* bp = x + (size_t)gbase;
        const float2* pu0 = (const float2*)(bp + e0);
        const float2* pv0 = (const float2*)(bp + f0);
        const float2* pu2 = (const float2*)(bp + e2);
        const float2* pv2 = (const float2*)(bp + f2);

        // Full unroll: one long pipelined burst of 8B loads per agent.
        // No shuffles, no divergence: taps come out via selects only.
#pragma unroll
        for (int c = 0; c < C_PER; c++) {
            const int coff2 = c * (HW / 2);
            const float2 u0 = __ldg(pu0 + coff2);
            const float2 v0 = __ldg(pv0 + coff2);
            const float2 u2 = __ldg(pu2 + coff2);
            const float2 v2 = __ldg(pv2 + coff2);

            const float t00 = odd ? u0.y : u0.x;                 // (x0,y0)
            const float t10 = odd ? u2.y : u2.x;                 // (x0,y1)
            const float t01 = dx ? (odd ? v0.x : u0.y) : t00;    // (x1,y0)
            const float t11 = dx ? (odd ? v2.x : u2.y) : t10;    // (x1,y1)

            float v = w0 * t00;
            v = fmaf(w1, t01, v);
            v = fmaf(w2, t10, v);
            v = fmaf(w3, t11, v);
            m[c] = fmaxf(m[c], v);
        }
    }

    float* op = out + (size_t)b * CHW + (size_t)c0 * HW + h * Wc + w;
#pragma unroll
    for (int c = 0; c < C_PER; c++)
        op[(size_t)c * HW] = m[c];
}

extern "C" void kernel_launch(void* const* d_in, const int* in_sizes, int n_in,
                              void* d_out, int out_size)
{
    // Inputs (metadata order): x, rm, record_len, pairwise_t_matrix
    const float* x    = (const float*)d_in[0];
    const float* tmat = (const float*)d_in[3];
    float* out = (float*)d_out;

    dim3 grid(Hc, Bc, C_CHUNKS);
    where2comm_fuse_kernel<<<grid, 256>>>(x, tmat, out, out_size);
}

// round 13
// speedup vs baseline: 1.9895x; 1.0593x over previous
#include <cuda_runtime.h>
#include <math.h>

#define Bc 4
#define Nc 5
#define Cc 64
#define Hc 100
#define Wc 252

static constexpr int HW  = Hc * Wc;      // 25200
static constexpr int CHW = Cc * HW;      // 1612800
static constexpr int OUT_MAIN = Bc * CHW;
static constexpr int C_CHUNKS = 8;
static constexpr int C_PER    = Cc / C_CHUNKS;   // 8

__global__ __launch_bounds__(256, 6) void where2comm_fuse_kernel(
    const float* __restrict__ x,          // [B*N, C, H, W]
    const float* __restrict__ tmat,       // [B, N, N, 2, 3]
    float* __restrict__ out,              // [B, C, H, W] (+ scalar tail)
    int out_size)
{
    const int h  = blockIdx.x;
    const int b  = blockIdx.y;
    const int c0 = blockIdx.z * C_PER;
    const int w  = threadIdx.x;

    // Zero any tail (communication_rates scalar) once.
    if (b == 0 && h == 0 && blockIdx.z == 0) {
        for (int i = OUT_MAIN + threadIdx.x; i < out_size; i += blockDim.x)
            out[i] = 0.0f;
    }
    if (w >= Wc) return;

    const float gx = (2.0f * (float)w + 1.0f) / (float)Wc - 1.0f;
    const float gy = (2.0f * (float)h + 1.0f) / (float)Hc - 1.0f;

    float m[C_PER];
#pragma unroll
    for (int c = 0; c < C_PER; c++) m[c] = -INFINITY;

#pragma unroll
    for (int n = 0; n < Nc; n++) {
        // theta = pairwise_t_matrix[b, 0, n, :, :]  -> 6 floats
        const float* th = tmat + ((size_t)b * Nc * Nc + n) * 6;
        const float t0 = __ldg(th + 0);
        const float t1 = __ldg(th + 1);
        const float t2 = __ldg(th + 2);
        const float t3 = __ldg(th + 3);
        const float t4 = __ldg(th + 4);
        const float t5 = __ldg(th + 5);

        const float cx = t0 * gx + t1 * gy + t2;
        const float cy = t3 * gx + t4 * gy + t5;
        const float ix = ((cx + 1.0f) * (float)Wc - 1.0f) * 0.5f;
        const float iy = ((cy + 1.0f) * (float)Hc - 1.0f) * 0.5f;

        const float x0f = floorf(ix);
        const float y0f = floorf(iy);
        const float wx1 = ix - x0f;
        const float wy1 = iy - y0f;
        const float wx0 = 1.0f - wx1;
        const float wy0 = 1.0f - wy1;

        const int x0 = (int)x0f;
        const int y0 = (int)y0f;
        const int x1 = x0 + 1;
        const int y1 = y0 + 1;

        const bool vx0 = (x0 >= 0) & (x0 <= Wc - 1);
        const bool vx1 = (x1 >= 0) & (x1 <= Wc - 1);
        const bool vy0 = (y0 >= 0) & (y0 <= Hc - 1);
        const bool vy1 = (y1 >= 0) & (y1 <= Hc - 1);

        const int x0c = min(max(x0, 0), Wc - 1);
        const int x1c = min(max(x1, 0), Wc - 1);
        const int y0c = min(max(y0, 0), Hc - 1);
        const int y1c = min(max(y1, 0), Hc - 1);

        // one 64-bit base pointer + four small int offsets (reg-lean)
        const float* bp = x + (size_t)((b * Nc + n) * CHW + c0 * HW);
        const int o0 = y0c * Wc + x0c;
        const int o1 = y0c * Wc + x1c;
        const int o2 = y1c * Wc + x0c;
        const int o3 = y1c * Wc + x1c;

        const float w0 = (vx0 && vy0) ? wx0 * wy0 : 0.0f;
        const float w1 = (vx1 && vy0) ? wx1 * wy0 : 0.0f;
        const float w2 = (vx0 && vy1) ? wx0 * wy1 : 0.0f;
        const float w3 = (vx1 && vy1) ? wx1 * wy1 : 0.0f;

        // Full unroll: one long pipelined load burst per agent. This shape
        // (32 scalar gather LDGs, ptxas-pipelined under a 42-reg cap) beat
        // every structural alternative tried in R5-R12; do not split it,
        // do not feed load results into shuffles, do not widen the loads.
#pragma unroll
        for (int c = 0; c < C_PER; c++) {
            const int coff = c * HW;
            float v = w0 * __ldg(bp + o0 + coff);
            v = fmaf(w1, __ldg(bp + o1 + coff), v);
            v = fmaf(w2, __ldg(bp + o2 + coff), v);
            v = fmaf(w3, __ldg(bp + o3 + coff), v);
            m[c] = fmaxf(m[c], v);
        }
    }

    float* op = out + (size_t)b * CHW + (size_t)c0 * HW + h * Wc + w;
#pragma unroll
    for (int c = 0; c < C_PER; c++)
        op[(size_t)c * HW] = m[c];
}

extern "C" void kernel_launch(void* const* d_in, const int* in_sizes, int n_in,
                              void* d_out, int out_size)
{
    // Inputs (metadata order): x, rm, record_len, pairwise_t_matrix
    const float* x    = (const float*)d_in[0];
    const float* tmat = (const float*)d_in[3];
    float* out = (float*)d_out;

    dim3 grid(Hc, Bc, C_CHUNKS);
    where2comm_fuse_kernel<<<grid, 256>>>(x, tmat, out, out_size);
}

// round 14
// speedup vs baseline: 2.0080x; 1.0093x over previous
#include <cuda_runtime.h>
#include <math.h>

#define Bc 4
#define Nc 5
#define Cc 64
#define Hc 100
#define Wc 252

static constexpr int HW  = Hc * Wc;      // 25200
static constexpr int CHW = Cc * HW;      // 1612800
static constexpr int OUT_MAIN = Bc * CHW;
static constexpr int C_CHUNKS = 8;
static constexpr int C_PER    = Cc / C_CHUNKS;   // 8

__global__ __launch_bounds__(256, 6) void where2comm_fuse_kernel(
    const float* __restrict__ x,          // [B*N, C, H, W]
    const float* __restrict__ tmat,       // [B, N, N, 2, 3]
    float* __restrict__ out,              // [B, C, H, W] (+ scalar tail)
    int out_size)
{
    const int h  = blockIdx.x;
    const int b  = blockIdx.y;
    const int c0 = blockIdx.z * C_PER;
    const int w  = threadIdx.x;

    // Zero any tail (communication_rates scalar) once.
    if (b == 0 && h == 0 && blockIdx.z == 0) {
        for (int i = OUT_MAIN + threadIdx.x; i < out_size; i += blockDim.x)
            out[i] = 0.0f;
    }
    if (w >= Wc) return;

    const float gx = (2.0f * (float)w + 1.0f) / (float)Wc - 1.0f;
    const float gy = (2.0f * (float)h + 1.0f) / (float)Hc - 1.0f;

    float m[C_PER];
#pragma unroll
    for (int c = 0; c < C_PER; c++) m[c] = -INFINITY;

#pragma unroll
    for (int n = 0; n < Nc; n++) {
        // theta = pairwise_t_matrix[b, 0, n, :, :]  -> 6 floats
        const float* th = tmat + ((size_t)b * Nc * Nc + n) * 6;
        const float t0 = __ldg(th + 0);
        const float t1 = __ldg(th + 1);
        const float t2 = __ldg(th + 2);
        const float t3 = __ldg(th + 3);
        const float t4 = __ldg(th + 4);
        const float t5 = __ldg(th + 5);

        const float cx = t0 * gx + t1 * gy + t2;
        const float cy = t3 * gx + t4 * gy + t5;
        const float ix = ((cx + 1.0f) * (float)Wc - 1.0f) * 0.5f;
        const float iy = ((cy + 1.0f) * (float)Hc - 1.0f) * 0.5f;

        const float x0f = floorf(ix);
        const float y0f = floorf(iy);
        const float wx1 = ix - x0f;
        const float wy1 = iy - y0f;
        const float wx0 = 1.0f - wx1;
        const float wy0 = 1.0f - wy1;

        const int x0 = (int)x0f;
        const int y0 = (int)y0f;
        const int x1 = x0 + 1;
        const int y1 = y0 + 1;

        const bool vx0 = (x0 >= 0) & (x0 <= Wc - 1);
        const bool vx1 = (x1 >= 0) & (x1 <= Wc - 1);
        const bool vy0 = (y0 >= 0) & (y0 <= Hc - 1);
        const bool vy1 = (y1 >= 0) & (y1 <= Hc - 1);

        const int x0c = min(max(x0, 0), Wc - 1);
        const int x1c = min(max(x1, 0), Wc - 1);
        const int y0c = min(max(y0, 0), Hc - 1);
        const int y1c = min(max(y1, 0), Hc - 1);

        // one 64-bit base pointer + four small int offsets (reg-lean)
        const float* bp = x + (size_t)((b * Nc + n) * CHW + c0 * HW);
        const int o0 = y0c * Wc + x0c;
        const int o1 = y0c * Wc + x1c;
        const int o2 = y1c * Wc + x0c;
        const int o3 = y1c * Wc + x1c;

        const float w0 = (vx0 && vy0) ? wx0 * wy0 : 0.0f;
        const float w1 = (vx1 && vy0) ? wx1 * wy0 : 0.0f;
        const float w2 = (vx0 && vy1) ? wx0 * wy1 : 0.0f;
        const float w3 = (vx1 && vy1) ? wx1 * wy1 : 0.0f;

        // Full unroll: one long pipelined load burst per agent. This shape
        // (32 scalar gather LDGs, ptxas-pipelined under a 42-reg cap) beat
        // every structural alternative tried in R5-R12; do not split it,
        // do not feed load results into shuffles, do not widen the loads.
#pragma unroll
        for (int c = 0; c < C_PER; c++) {
            const int coff = c * HW;
            float v = w0 * __ldg(bp + o0 + coff);
            v = fmaf(w1, __ldg(bp + o1 + coff), v);
            v = fmaf(w2, __ldg(bp + o2 + coff), v);
            v = fmaf(w3, __ldg(bp + o3 + coff), v);
            m[c] = fmaxf(m[c], v);
        }
    }

    float* op = out + (size_t)b * CHW + (size_t)c0 * HW + h * Wc + w;
#pragma unroll
    for (int c = 0; c < C_PER; c++)
        op[(size_t)c * HW] = m[c];
}

extern "C" void kernel_launch(void* const* d_in, const int* in_sizes, int n_in,
                              void* d_out, int out_size)
{
    // Inputs (metadata order): x, rm, record_len, pairwise_t_matrix
    const float* x    = (const float*)d_in[0];
    const float* tmat = (const float*)d_in[3];
    float* out = (float*)d_out;

    // Maximize the L1D carveout (0 smem used): host attribute call, not a
    // stream op -> graph-capture safe, allocation-free, deterministic.
    cudaFuncSetAttribute(where2comm_fuse_kernel,
                         cudaFuncAttributePreferredSharedMemoryCarveout,
                         cudaSharedmemCarveoutMaxL1);

    dim3 grid(Hc, Bc, C_CHUNKS);
    where2comm_fuse_kernel<<<grid, 256>>>(x, tmat, out, out_size);
}

// round 15
// speedup vs baseline: 2.0489x; 1.0204x over previous
#include <cuda_runtime.h>
#include <math.h>

#define Bc 4
#define Nc 5
#define Cc 64
#define Hc 100
#define Wc 252

static constexpr int HW  = Hc * Wc;      // 25200
static constexpr int CHW = Cc * HW;      // 1612800
static constexpr int OUT_MAIN = Bc * CHW;
static constexpr int C_CHUNKS = 8;
static constexpr int C_PER    = Cc / C_CHUNKS;   // 8
static constexpr int H_PER    = 2;               // h rows per CTA (L1 tap reuse)

__global__ __launch_bounds__(512, 3) void where2comm_fuse_kernel(
    const float* __restrict__ x,          // [B*N, C, H, W]
    const float* __restrict__ tmat,       // [B, N, N, 2, 3]
    float* __restrict__ out,              // [B, C, H, W] (+ scalar tail)
    int out_size)
{
    // 512 threads = 2 adjacent h rows x 256 lanes. Adjacent rows share ~half
    // their bilinear tap lines (theta ~ identity); co-residency on one SM
    // converts those re-reads from L2 hits (~240cyc) into L1 hits (~32cyc).
    const int h  = blockIdx.x * H_PER + (threadIdx.x >> 8);
    const int b  = blockIdx.y;
    const int c0 = blockIdx.z * C_PER;
    const int w  = threadIdx.x & 255;

    // Zero any tail (communication_rates scalar) once.
    if (blockIdx.x == 0 && b == 0 && blockIdx.z == 0) {
        for (int i = OUT_MAIN + threadIdx.x; i < out_size; i += blockDim.x)
            out[i] = 0.0f;
    }
    if (w >= Wc) return;

    const float gx = (2.0f * (float)w + 1.0f) / (float)Wc - 1.0f;
    const float gy = (2.0f * (float)h + 1.0f) / (float)Hc - 1.0f;

    float m[C_PER];
#pragma unroll
    for (int c = 0; c < C_PER; c++) m[c] = -INFINITY;

#pragma unroll
    for (int n = 0; n < Nc; n++) {
        // theta = pairwise_t_matrix[b, 0, n, :, :]  -> 6 floats
        const float* th = tmat + ((size_t)b * Nc * Nc + n) * 6;
        const float t0 = __ldg(th + 0);
        const float t1 = __ldg(th + 1);
        const float t2 = __ldg(th + 2);
        const float t3 = __ldg(th + 3);
        const float t4 = __ldg(th + 4);
        const float t5 = __ldg(th + 5);

        const float cx = t0 * gx + t1 * gy + t2;
        const float cy = t3 * gx + t4 * gy + t5;
        const float ix = ((cx + 1.0f) * (float)Wc - 1.0f) * 0.5f;
        const float iy = ((cy + 1.0f) * (float)Hc - 1.0f) * 0.5f;

        const float x0f = floorf(ix);
        const float y0f = floorf(iy);
        const float wx1 = ix - x0f;
        const float wy1 = iy - y0f;
        const float wx0 = 1.0f - wx1;
        const float wy0 = 1.0f - wy1;

        const int x0 = (int)x0f;
        const int y0 = (int)y0f;
        const int x1 = x0 + 1;
        const int y1 = y0 + 1;

        const bool vx0 = (x0 >= 0) & (x0 <= Wc - 1);
        const bool vx1 = (x1 >= 0) & (x1 <= Wc - 1);
        const bool vy0 = (y0 >= 0) & (y0 <= Hc - 1);
        const bool vy1 = (y1 >= 0) & (y1 <= Hc - 1);

        const int x0c = min(max(x0, 0), Wc - 1);
        const int x1c = min(max(x1, 0), Wc - 1);
        const int y0c = min(max(y0, 0), Hc - 1);
        const int y1c = min(max(y1, 0), Hc - 1);

        // one 64-bit base pointer + four small int offsets (reg-lean)
        const float* bp = x + (size_t)((b * Nc + n) * CHW + c0 * HW);
        const int o0 = y0c * Wc + x0c;
        const int o1 = y0c * Wc + x1c;
        const int o2 = y1c * Wc + x0c;
        const int o3 = y1c * Wc + x1c;

        const float w0 = (vx0 && vy0) ? wx0 * wy0 : 0.0f;
        const float w1 = (vx1 && vy0) ? wx1 * wy0 : 0.0f;
        const float w2 = (vx0 && vy1) ? wx0 * wy1 : 0.0f;
        const float w3 = (vx1 && vy1) ? wx1 * wy1 : 0.0f;

        // Full unroll: one long pipelined load burst per agent. This shape
        // (32 scalar gather LDGs, ptxas-pipelined under a ~40-reg budget)
        // beat every structural alternative in R5-R12; do not split it,
        // do not feed load results into shuffles, do not widen the loads.
#pragma unroll
        for (int c = 0; c < C_PER; c++) {
            const int coff = c * HW;
            float v = w0 * __ldg(bp + o0 + coff);
            v = fmaf(w1, __ldg(bp + o1 + coff), v);
            v = fmaf(w2, __ldg(bp + o2 + coff), v);
            v = fmaf(w3, __ldg(bp + o3 + coff), v);
            m[c] = fmaxf(m[c], v);
        }
    }

    float* op = out + (size_t)b * CHW + (size_t)c0 * HW + h * Wc + w;
#pragma unroll
    for (int c = 0; c < C_PER; c++)
        op[(size_t)c * HW] = m[c];
}

extern "C" void kernel_launch(void* const* d_in, const int* in_sizes, int n_in,
                              void* d_out, int out_size)
{
    // Inputs (metadata order): x, rm, record_len, pairwise_t_matrix
    const float* x    = (const float*)d_in[0];
    const float* tmat = (const float*)d_in[3];
    float* out = (float*)d_out;

    // Maximize the L1D carveout (0 smem used): host attribute call, not a
    // stream op -> graph-capture safe, allocation-free, deterministic.
    cudaFuncSetAttribute(where2comm_fuse_kernel,
                         cudaFuncAttributePreferredSharedMemoryCarveout,
                         cudaSharedmemCarveoutMaxL1);

    dim3 grid(Hc / H_PER, Bc, C_CHUNKS);
    where2comm_fuse_kernel<<<grid, 512>>>(x, tmat, out, out_size);
}